// round 1
// baseline (speedup 1.0000x reference)
#include <cuda_runtime.h>

// SOPTD: two tiny MLPs + scalar ODE arithmetic. One warp does everything.
//
// Input order (metadata.txt):
//  0:t  1:states  2:W1 3:b1  4:W2 5:b2  6:W3 7:b3  8:W4 9:b4
//  10:W5 11:b5  12:W6 13:b6  14:W7 15:b7  16:W8 17:b8
//  18:Kp1 19:Kp2 20:Tau1 21:Tau2 22:z1 23:z2
// Output: 5 float32.

__global__ __launch_bounds__(32, 1)
void soptd_kernel(const float* __restrict__ states,
                  const float* __restrict__ W1, const float* __restrict__ b1,
                  const float* __restrict__ W2, const float* __restrict__ b2,
                  const float* __restrict__ W3, const float* __restrict__ b3,
                  const float* __restrict__ W4, const float* __restrict__ b4,
                  const float* __restrict__ W5, const float* __restrict__ b5,
                  const float* __restrict__ W6, const float* __restrict__ b6,
                  const float* __restrict__ W7, const float* __restrict__ b7,
                  const float* __restrict__ W8, const float* __restrict__ b8,
                  const float* __restrict__ pKp1, const float* __restrict__ pKp2,
                  const float* __restrict__ pTau1, const float* __restrict__ pTau2,
                  const float* __restrict__ pz1,  const float* __restrict__ pz2,
                  float* __restrict__ out)
{
    const unsigned FULL = 0xffffffffu;
    const int j = threadIdx.x;           // 0..31, one hidden unit per lane

    // ---- load state (every lane; 5 floats, L1/L2-coalesced) ----
    const float u    = states[0];
    const float x1   = states[1];
    const float x2   = states[2];
    const float x1_p = states[3];
    const float x2_p = states[4];

    // =========== MLP 1: [u,x1,x2] -> 4 -> 32 -> 32 -> 2 ===========
    // Layer 1 (linear, width 4): computed redundantly per lane (12 FMAs).
    float h1[4];
#pragma unroll
    for (int c = 0; c < 4; ++c)
        h1[c] = fmaf(u, W1[0*4+c], fmaf(x1, W1[1*4+c], fmaf(x2, W1[2*4+c], b1[c])));

    // Layer 2 (tanh, 4 -> 32): lane j owns column j.
    float h2 = b2[j];
#pragma unroll
    for (int k = 0; k < 4; ++k)
        h2 = fmaf(h1[k], W2[k*32 + j], h2);
    h2 = tanhf(h2);

    // Layer 3 (tanh, 32 -> 32): shuffle-broadcast reduction.
    float h3 = b3[j];
#pragma unroll
    for (int k = 0; k < 32; ++k)
        h3 = fmaf(__shfl_sync(FULL, h2, k), W3[k*32 + j], h3);
    h3 = tanhf(h3);

    // Layer 4 (linear, 32 -> 2): each lane contributes, butterfly-reduce.
    float p0 = h3 * W4[j*2 + 0];
    float p1 = h3 * W4[j*2 + 1];
#pragma unroll
    for (int off = 16; off > 0; off >>= 1) {
        p0 += __shfl_xor_sync(FULL, p0, off);
        p1 += __shfl_xor_sync(FULL, p1, off);
    }
    const float u60 = p0 + b4[0];
    const float u61 = p1 + b4[1];

    // =========== scalar ODE arithmetic (every lane, identical) ===========
    const float Kp1  = *pKp1,  Kp2  = *pKp2;
    const float Tau1 = *pTau1, Tau2 = *pTau2;
    const float z1   = *pz1,   z2   = *pz2;

    const float inv_t1 = 1.0f / Tau1;
    const float inv_t2 = 1.0f / Tau2;

    const float x1_dot   = x1_p;
    const float x1_p_dot = (Kp1 * inv_t1 * u60 - 2.0f * (z1 * x1) - x1_p * inv_t1) * inv_t1;
    const float x2_dot   = x2_p;
    const float x2_p_dot = (Kp2 * inv_t2 * u61 - 2.0f * (z2 * x2) - x2_p * inv_t2) * inv_t2;

    const float xd[5] = { x1_dot, x2_dot, x1_p_dot, x2_p_dot, u };

    // =========== MLP 2: [5] -> 32 -> 32 -> 32 -> 4 ===========
    // Layer 5 (linear, 5 -> 32): lane j owns column j.
    float g1 = b5[j];
#pragma unroll
    for (int k = 0; k < 5; ++k)
        g1 = fmaf(xd[k], W5[k*32 + j], g1);

    // Layer 6 (tanh, 32 -> 32)
    float g2 = b6[j];
#pragma unroll
    for (int k = 0; k < 32; ++k)
        g2 = fmaf(__shfl_sync(FULL, g1, k), W6[k*32 + j], g2);
    g2 = tanhf(g2);

    // Layer 7 (tanh, 32 -> 32)
    float g3 = b7[j];
#pragma unroll
    for (int k = 0; k < 32; ++k)
        g3 = fmaf(__shfl_sync(FULL, g2, k), W7[k*32 + j], g3);
    g3 = tanhf(g3);

    // Layer 8 (linear, 32 -> 4): butterfly-reduce 4 partials.
    float q0 = g3 * W8[j*4 + 0];
    float q1 = g3 * W8[j*4 + 1];
    float q2 = g3 * W8[j*4 + 2];
    float q3 = g3 * W8[j*4 + 3];
#pragma unroll
    for (int off = 16; off > 0; off >>= 1) {
        q0 += __shfl_xor_sync(FULL, q0, off);
        q1 += __shfl_xor_sync(FULL, q1, off);
        q2 += __shfl_xor_sync(FULL, q2, off);
        q3 += __shfl_xor_sync(FULL, q3, off);
    }

    if (j == 0) {
        out[0] = 0.0f;
        out[1] = q0 + b8[0];
        out[2] = q1 + b8[1];
        out[3] = q2 + b8[2];
        out[4] = q3 + b8[3];
    }
}

extern "C" void kernel_launch(void* const* d_in, const int* in_sizes, int n_in,
                              void* d_out, int out_size)
{
    (void)in_sizes; (void)n_in; (void)out_size;
    soptd_kernel<<<1, 32>>>(
        (const float*)d_in[1],                       // states  (d_in[0] = t, unused)
        (const float*)d_in[2],  (const float*)d_in[3],   // W1 b1
        (const float*)d_in[4],  (const float*)d_in[5],   // W2 b2
        (const float*)d_in[6],  (const float*)d_in[7],   // W3 b3
        (const float*)d_in[8],  (const float*)d_in[9],   // W4 b4
        (const float*)d_in[10], (const float*)d_in[11],  // W5 b5
        (const float*)d_in[12], (const float*)d_in[13],  // W6 b6
        (const float*)d_in[14], (const float*)d_in[15],  // W7 b7
        (const float*)d_in[16], (const float*)d_in[17],  // W8 b8
        (const float*)d_in[18], (const float*)d_in[19],  // Kp1 Kp2
        (const float*)d_in[20], (const float*)d_in[21],  // Tau1 Tau2
        (const float*)d_in[22], (const float*)d_in[23],  // z1 z2
        (float*)d_out);
}